// round 4
// baseline (speedup 1.0000x reference)
#include <cuda_runtime.h>
#include <cstddef>

// ---------------------------------------------------------------------------
// SSIM loss, fused single-pass:
//   5 depthwise 11x11 Gaussian blurs (separable) + SSIM map + mean, one kernel.
//   x,y: (48 planes) x 512 x 512 fp32. Output: scalar float = 1 - mean(ssim).
// ---------------------------------------------------------------------------

#define IMG_H 512
#define IMG_W 512

// Output tile 128x16, halo 5 each side.
#define TX 128
#define TY 16
#define RX 138          // TX + 10
#define RY 26           // TY + 10
#define RXP 140         // padded row stride (floats), keeps float4 alignment
#define SMEM_RAW (RY * RXP)       // 3640 floats per raw array
#define SMEM_V   (TY * RXP)       // 2240 floats per v-blurred array
#define SMEM_FLOATS (2 * SMEM_RAW + 5 * SMEM_V)   // 18480
#define SMEM_BYTES  (SMEM_FLOATS * 4)             // 73920

// Normalized Gaussian taps, sigma=1.5, window=11 (precomputed, symmetric).
// Literal constants -> ptxas emits FFMA with immediate multiplier (rt=1).
#define G0 0.00102838f
#define G1 0.00759874f
#define G2 0.03600077f
#define G3 0.10936069f
#define G4 0.21300553f
#define G5 0.26601172f
__device__ __constant__ float Gc[11] = {G0,G1,G2,G3,G4,G5,G4,G3,G2,G1,G0};

__device__ double g_accum;

__global__ void zero_acc_kernel() { g_accum = 0.0; }

__global__ void finalize_kernel(float* out, float inv_n) {
    out[0] = 1.0f - (float)(g_accum) * inv_n;
}

// 11-tap weighted sum with static indices (immediates).
#define TAP11(dst, arr, off)                                   \
    do {                                                       \
        float _s = G0 * (arr)[(off) + 0];                      \
        _s = fmaf(G1, (arr)[(off) + 1], _s);                   \
        _s = fmaf(G2, (arr)[(off) + 2], _s);                   \
        _s = fmaf(G3, (arr)[(off) + 3], _s);                   \
        _s = fmaf(G4, (arr)[(off) + 4], _s);                   \
        _s = fmaf(G5, (arr)[(off) + 5], _s);                   \
        _s = fmaf(G4, (arr)[(off) + 6], _s);                   \
        _s = fmaf(G3, (arr)[(off) + 7], _s);                   \
        _s = fmaf(G2, (arr)[(off) + 8], _s);                   \
        _s = fmaf(G1, (arr)[(off) + 9], _s);                   \
        _s = fmaf(G0, (arr)[(off) + 10], _s);                  \
        (dst) = _s;                                            \
    } while (0)

__global__ void __launch_bounds__(256, 3)
ssim_fused_kernel(const float* __restrict__ x, const float* __restrict__ y) {
    extern __shared__ float sm[];
    float* __restrict__ sxp = sm;                  // [RY][RXP] raw x
    float* __restrict__ syp = sm + SMEM_RAW;       // [RY][RXP] raw y
    float* __restrict__ vp  = sm + 2 * SMEM_RAW;   // [5][TY][RXP] v-blurred

    const int tid   = threadIdx.x;
    const int plane = blockIdx.z;
    const int row0  = (int)blockIdx.y * TY - 5;
    const int col0  = (int)blockIdx.x * TX - 5;

    const float* __restrict__ xb = x + (size_t)plane * (IMG_H * IMG_W);
    const float* __restrict__ yb = y + (size_t)plane * (IMG_H * IMG_W);

    // ---- Phase A: load raw tile (zero padding outside image) --------------
    for (int i = tid; i < RY * RX; i += 256) {
        int r = i / RX;
        int c = i - r * RX;
        int gr = row0 + r;
        int gc = col0 + c;
        float xv = 0.0f, yv = 0.0f;
        if ((unsigned)gr < IMG_H && (unsigned)gc < IMG_W) {
            int gi = gr * IMG_W + gc;
            xv = __ldg(xb + gi);
            yv = __ldg(yb + gi);
        }
        sxp[r * RXP + c] = xv;
        syp[r * RXP + c] = yv;
    }
    __syncthreads();

    // ---- Phase B: vertical blur of 5 quantities -> vp ---------------------
    // task = (quantity q, column col); 5*138 = 690 tasks over 256 threads.
    for (int task = tid; task < 5 * RX; task += 256) {
        int col = task % RX;
        int q   = task / RX;
        float val[RY];
#pragma unroll
        for (int ri = 0; ri < RY; ++ri) {
            float a = sxp[ri * RXP + col];
            float b = syp[ri * RXP + col];
            float v0 = (q == 0) ? a
                     : (q == 1) ? b
                     : (q == 2) ? a * a
                     : (q == 3) ? b * b
                                : a * b;
            val[ri] = v0;
        }
        float* __restrict__ vq = vp + q * SMEM_V + col;
#pragma unroll
        for (int r = 0; r < TY; ++r) {
            float s;
            TAP11(s, val, r);
            vq[r * RXP] = s;
        }
    }
    __syncthreads();

    // ---- Phase C: horizontal blur + SSIM + local sum ----------------------
    // One task per thread: (row = tid/16, 8-column chunk = tid%16).
    const int row = tid >> 4;
    const int c0  = (tid & 15) << 3;

    float res[5][8];
#pragma unroll
    for (int q = 0; q < 5; ++q) {
        const float* __restrict__ base = vp + q * SMEM_V + row * RXP + c0;
        float w[20];
#pragma unroll
        for (int k = 0; k < 5; ++k) {
            float4 t4 = *reinterpret_cast<const float4*>(base + 4 * k);
            w[4 * k + 0] = t4.x;
            w[4 * k + 1] = t4.y;
            w[4 * k + 2] = t4.z;
            w[4 * k + 3] = t4.w;
        }
#pragma unroll
        for (int j = 0; j < 8; ++j) {
            TAP11(res[q][j], w, j);
        }
    }

    const float C1 = 1e-4f;   // (0.01*1)^2
    const float C2 = 9e-4f;   // (0.03*1)^2
    float lsum = 0.0f;
#pragma unroll
    for (int j = 0; j < 8; ++j) {
        float mux  = res[0][j];
        float muy  = res[1][j];
        float mux2 = mux * mux;
        float muy2 = muy * muy;
        float muxy = mux * muy;
        float sx_  = res[2][j] - mux2;
        float sy_  = res[3][j] - muy2;
        float sxy_ = res[4][j] - muxy;
        float num = (2.0f * muxy + C1) * (2.0f * sxy_ + C2);
        float den = (mux2 + muy2 + C1) * (sx_ + sy_ + C2) + 1e-8f;
        lsum += __fdividef(num, den);
    }

    // ---- Block reduction + one double atomic per block --------------------
#pragma unroll
    for (int o = 16; o; o >>= 1)
        lsum += __shfl_xor_sync(0xffffffffu, lsum, o);

    __shared__ float wsum[8];
    if ((tid & 31) == 0) wsum[tid >> 5] = lsum;
    __syncthreads();
    if (tid == 0) {
        float t = 0.0f;
#pragma unroll
        for (int i = 0; i < 8; ++i) t += wsum[i];
        atomicAdd(&g_accum, (double)t);
    }
}

extern "C" void kernel_launch(void* const* d_in, const int* in_sizes, int n_in,
                              void* d_out, int out_size) {
    const float* x = (const float*)d_in[0];
    const float* y = (const float*)d_in[1];
    float* out = (float*)d_out;

    const int planes = in_sizes[0] / (IMG_H * IMG_W);   // 48 = 16 batch * 3 ch
    const float inv_n = 1.0f / (float)in_sizes[0];

    // Idempotent, host-side only; required for 73.9KB dynamic smem.
    cudaFuncSetAttribute(ssim_fused_kernel,
                         cudaFuncAttributeMaxDynamicSharedMemorySize,
                         SMEM_BYTES);

    zero_acc_kernel<<<1, 1>>>();

    dim3 grid(IMG_W / TX, IMG_H / TY, planes);   // 4 x 32 x 48 = 6144 blocks
    ssim_fused_kernel<<<grid, 256, SMEM_BYTES>>>(x, y);

    finalize_kernel<<<1, 1>>>(out, inv_n);
}

// round 7
// speedup vs baseline: 1.2679x; 1.2679x over previous
#include <cuda_runtime.h>
#include <cstddef>

// ---------------------------------------------------------------------------
// SSIM loss, fully fused single kernel:
//   5 separable 11x11 Gaussian blurs + SSIM map + mean, last block finalizes.
//   x,y: (48 planes) x 512 x 512 fp32. out[0] = 1 - mean(ssim).
// ---------------------------------------------------------------------------

#define IMG_H 512
#define IMG_W 512

// Output tile 128x16, halo 5 each side.
#define TX 128
#define TY 16
#define RX 138          // TX + 10
#define RY 26           // TY + 10
#define RXP 140         // padded row stride (floats), float4-aligned
#define SMEM_RAW (RY * RXP)       // 3640 floats per raw array
#define SMEM_V   (TY * RXP)       // 2240 floats per v-blurred array
#define SMEM_FLOATS (2 * SMEM_RAW + 5 * SMEM_V)   // 18480
#define SMEM_BYTES  (SMEM_FLOATS * 4)             // 73920 -> 3 blocks/SM

// Gaussian taps, sigma=1.5, window=11 (immediates -> FFMA-imm, rt=1).
#define G0 0.00102838f
#define G1 0.00759874f
#define G2 0.03600077f
#define G3 0.10936069f
#define G4 0.21300553f
#define G5 0.26601172f

__device__ double g_accum;          // zero-init at module load; reset each launch
__device__ unsigned int g_ticket;   // ditto

// 11-tap weighted sum, static indices.
#define TAP11(dst, arr, off)                                   \
    do {                                                       \
        float _s = G0 * (arr)[(off) + 0];                      \
        _s = fmaf(G1, (arr)[(off) + 1], _s);                   \
        _s = fmaf(G2, (arr)[(off) + 2], _s);                   \
        _s = fmaf(G3, (arr)[(off) + 3], _s);                   \
        _s = fmaf(G4, (arr)[(off) + 4], _s);                   \
        _s = fmaf(G5, (arr)[(off) + 5], _s);                   \
        _s = fmaf(G4, (arr)[(off) + 6], _s);                   \
        _s = fmaf(G3, (arr)[(off) + 7], _s);                   \
        _s = fmaf(G2, (arr)[(off) + 8], _s);                   \
        _s = fmaf(G1, (arr)[(off) + 9], _s);                   \
        _s = fmaf(G0, (arr)[(off) + 10], _s);                  \
        (dst) = _s;                                            \
    } while (0)

// Vertical blur of one column: writes blur(src) and blur(src^2).
// Loads the column once (26 LDS), peak ~30 live regs.
__device__ __forceinline__ void vblur_sq(const float* __restrict__ src,
                                         float* __restrict__ vlin,
                                         float* __restrict__ vsq, int col) {
    float a[RY];
#pragma unroll
    for (int r = 0; r < RY; ++r) a[r] = src[r * RXP + col];
#pragma unroll
    for (int r = 0; r < TY; ++r) { float s; TAP11(s, a, r); vlin[r * RXP + col] = s; }
#pragma unroll
    for (int r = 0; r < RY; ++r) a[r] *= a[r];
#pragma unroll
    for (int r = 0; r < TY; ++r) { float s; TAP11(s, a, r); vsq[r * RXP + col] = s; }
}

__global__ void __launch_bounds__(256, 3)
ssim_fused_kernel(const float* __restrict__ x, const float* __restrict__ y,
                  float* __restrict__ out, float inv_n) {
    extern __shared__ float sm[];
    float* __restrict__ sxp = sm;                  // [RY][RXP] raw x
    float* __restrict__ syp = sm + SMEM_RAW;       // [RY][RXP] raw y
    float* __restrict__ vp  = sm + 2 * SMEM_RAW;   // [5][TY][RXP]: mux,muy,xx,yy,xy

    const int tid   = threadIdx.x;
    const int plane = blockIdx.z;
    const int row0  = (int)blockIdx.y * TY - 5;
    const int col0  = (int)blockIdx.x * TX - 5;

    const float* __restrict__ xb = x + (size_t)plane * (IMG_H * IMG_W);
    const float* __restrict__ yb = y + (size_t)plane * (IMG_H * IMG_W);

    // ---- Phase A: raw tile load (zero padding outside image) --------------
    for (int i = tid; i < RY * RX; i += 256) {
        int r = i / RX;
        int c = i - r * RX;
        int gr = row0 + r;
        int gc = col0 + c;
        float xv = 0.0f, yv = 0.0f;
        if ((unsigned)gr < IMG_H && (unsigned)gc < IMG_W) {
            int gi = gr * IMG_W + gc;
            xv = __ldg(xb + gi);
            yv = __ldg(yb + gi);
        }
        sxp[r * RXP + c] = xv;
        syp[r * RXP + c] = yv;
    }
    __syncthreads();

    // ---- Phase B: vertical blur, merged per-column groups -----------------
    // group 0: x -> mux, xx ; group 1: y -> muy, yy ; group 2: xy -> xy
    // 3*138 = 414 tasks over 256 threads; raw column loaded once per group.
    for (int task = tid; task < 3 * RX; task += 256) {
        int g   = task / RX;
        int col = task - g * RX;
        if (g == 0) {
            vblur_sq(sxp, vp + 0 * SMEM_V, vp + 2 * SMEM_V, col);
        } else if (g == 1) {
            vblur_sq(syp, vp + 1 * SMEM_V, vp + 3 * SMEM_V, col);
        } else {
            float a[RY];
#pragma unroll
            for (int r = 0; r < RY; ++r)
                a[r] = sxp[r * RXP + col] * syp[r * RXP + col];
            float* __restrict__ v4 = vp + 4 * SMEM_V + col;
#pragma unroll
            for (int r = 0; r < TY; ++r) { float s; TAP11(s, a, r); v4[r * RXP + col - col] = s, v4[r * RXP] = s; }
        }
    }
    __syncthreads();

    // ---- Phase C: horizontal blur + SSIM ----------------------------------
    // Task = (row, 4-col chunk): 16*32 = 512 tasks, exactly 2 per thread.
    // Lane stride 16B -> conflict-free LDS.128.
    const float C1 = 1e-4f;   // (0.01*1)^2
    const float C2 = 9e-4f;   // (0.03*1)^2
    float lsum = 0.0f;

#pragma unroll
    for (int it = 0; it < 2; ++it) {
        int T   = it * 256 + tid;
        int row = T >> 5;
        int c0  = (T & 31) << 2;

        float res[5][4];
#pragma unroll
        for (int q = 0; q < 5; ++q) {
            const float* __restrict__ base = vp + q * SMEM_V + row * RXP + c0;
            float w[16];
#pragma unroll
            for (int k = 0; k < 4; ++k) {
                float4 t4 = *reinterpret_cast<const float4*>(base + 4 * k);
                w[4 * k + 0] = t4.x;
                w[4 * k + 1] = t4.y;
                w[4 * k + 2] = t4.z;
                w[4 * k + 3] = t4.w;
            }
#pragma unroll
            for (int j = 0; j < 4; ++j) TAP11(res[q][j], w, j);
        }

#pragma unroll
        for (int j = 0; j < 4; ++j) {
            float mux  = res[0][j];
            float muy  = res[1][j];
            float mux2 = mux * mux;
            float muy2 = muy * muy;
            float muxy = mux * muy;
            float sx_  = res[2][j] - mux2;
            float sy_  = res[3][j] - muy2;
            float sxy_ = res[4][j] - muxy;
            float num = (2.0f * muxy + C1) * (2.0f * sxy_ + C2);
            float den = (mux2 + muy2 + C1) * (sx_ + sy_ + C2) + 1e-8f;
            lsum += __fdividef(num, den);
        }
    }

    // ---- Block reduce + global accumulate + last-block finalize -----------
#pragma unroll
    for (int o = 16; o; o >>= 1)
        lsum += __shfl_xor_sync(0xffffffffu, lsum, o);

    __shared__ float wsum[8];
    if ((tid & 31) == 0) wsum[tid >> 5] = lsum;
    __syncthreads();
    if (tid == 0) {
        float t = 0.0f;
#pragma unroll
        for (int i = 0; i < 8; ++i) t += wsum[i];
        atomicAdd(&g_accum, (double)t);
        __threadfence();
        unsigned int nb = gridDim.x * gridDim.y * gridDim.z;
        unsigned int tk = atomicAdd(&g_ticket, 1u);
        if (tk == nb - 1u) {
            double total = atomicAdd(&g_accum, 0.0);   // atomic read (L2)
            out[0] = 1.0f - (float)(total * (double)inv_n);
            // Reset for next graph replay (deterministic across replays).
            g_accum  = 0.0;
            g_ticket = 0u;
        }
    }
}

extern "C" void kernel_launch(void* const* d_in, const int* in_sizes, int n_in,
                              void* d_out, int out_size) {
    const float* x = (const float*)d_in[0];
    const float* y = (const float*)d_in[1];
    float* out = (float*)d_out;

    const int planes = in_sizes[0] / (IMG_H * IMG_W);   // 48 = 16 batch * 3 ch
    const float inv_n = 1.0f / (float)in_sizes[0];

    // Idempotent host-side attribute set (needed for 73.9 KB dynamic smem).
    cudaFuncSetAttribute(ssim_fused_kernel,
                         cudaFuncAttributeMaxDynamicSharedMemorySize,
                         SMEM_BYTES);

    dim3 grid(IMG_W / TX, IMG_H / TY, planes);   // 4 x 32 x 48 = 6144 blocks
    ssim_fused_kernel<<<grid, 256, SMEM_BYTES>>>(x, y, out, inv_n);
}

// round 9
// speedup vs baseline: 2.2319x; 1.7604x over previous
#include <cuda_runtime.h>
#include <cstddef>

// ---------------------------------------------------------------------------
// SSIM loss, fully fused single kernel (v3):
//   vertical blur: global -> registers -> smem (no raw smem tile)
//   horizontal blur + SSIM + block reduce; last block finalizes.
//   x,y: (48 planes) x 512 x 512 fp32. out[0] = 1 - mean(ssim).
// ---------------------------------------------------------------------------

#define IMG_H 512
#define IMG_W 512

// Output tile 128x16, halo 5 each side.
#define TX 128
#define TY 16
#define RX 138          // TX + 10 columns needed (with halo)
#define RY 26           // TY + 10 rows needed
#define RXP 140         // padded row stride (floats), float4-aligned
#define SMEM_V   (TY * RXP)            // 2240 floats per v-blurred array
#define SMEM_FLOATS (5 * SMEM_V)       // 11200
#define SMEM_BYTES  (SMEM_FLOATS * 4)  // 44800 -> 5 blocks/SM

// Warp-aligned group stride for vertical-blur tasks (RX=138 -> pad to 160).
#define GSTRIDE 160

// Gaussian taps, sigma=1.5, window=11 (immediates -> FFMA-imm, rt=1).
#define G0 0.00102838f
#define G1 0.00759874f
#define G2 0.03600077f
#define G3 0.10936069f
#define G4 0.21300553f
#define G5 0.26601172f

__device__ double g_accum;          // zero-init at load; reset by last block
__device__ unsigned int g_ticket;   // ditto

// 11-tap weighted sum, static indices.
#define TAP11(dst, arr, off)                                   \
    do {                                                       \
        float _s = G0 * (arr)[(off) + 0];                      \
        _s = fmaf(G1, (arr)[(off) + 1], _s);                   \
        _s = fmaf(G2, (arr)[(off) + 2], _s);                   \
        _s = fmaf(G3, (arr)[(off) + 3], _s);                   \
        _s = fmaf(G4, (arr)[(off) + 4], _s);                   \
        _s = fmaf(G5, (arr)[(off) + 5], _s);                   \
        _s = fmaf(G4, (arr)[(off) + 6], _s);                   \
        _s = fmaf(G3, (arr)[(off) + 7], _s);                   \
        _s = fmaf(G2, (arr)[(off) + 8], _s);                   \
        _s = fmaf(G1, (arr)[(off) + 9], _s);                   \
        _s = fmaf(G0, (arr)[(off) + 10], _s);                  \
        (dst) = _s;                                            \
    } while (0)

__global__ void __launch_bounds__(256, 5)
ssim_fused_kernel(const float* __restrict__ x, const float* __restrict__ y,
                  float* __restrict__ out, float inv_n) {
    extern __shared__ float sm[];
    float* __restrict__ vp = sm;   // [5][TY][RXP]: mux, muy, xx, yy, xy

    const int tid   = threadIdx.x;
    const int plane = blockIdx.z;
    const int row0  = (int)blockIdx.y * TY - 5;
    const int col0  = (int)blockIdx.x * TX - 5;

    const float* __restrict__ xb = x + (size_t)plane * (IMG_H * IMG_W);
    const float* __restrict__ yb = y + (size_t)plane * (IMG_H * IMG_W);

    // ---- Phase AB: vertical blur, global -> registers -> smem -------------
    // Task space padded to 3 warp-aligned groups of GSTRIDE:
    //   group 0: x  -> mux (v0), xx (v2)
    //   group 1: y  -> muy (v1), yy (v3)
    //   group 2: xy -> xy  (v4)
    // Consecutive threads take consecutive columns -> coalesced LDG per row.
    for (int task = tid; task < 3 * GSTRIDE; task += 256) {
        const int g   = task / GSTRIDE;
        const int col = task - g * GSTRIDE;
        if (col >= RX) continue;
        const int gc = col0 + col;
        const bool inw = (unsigned)gc < IMG_W;

        float a[RY];
        if (g == 2) {
#pragma unroll
            for (int r = 0; r < RY; ++r) {
                int gr = row0 + r;
                bool ok = inw && ((unsigned)gr < IMG_H);
                float xv = ok ? __ldg(xb + gr * IMG_W + gc) : 0.0f;
                float yv = ok ? __ldg(yb + gr * IMG_W + gc) : 0.0f;
                a[r] = xv * yv;
            }
            float* __restrict__ v4 = vp + 4 * SMEM_V + col;
#pragma unroll
            for (int r = 0; r < TY; ++r) { float s; TAP11(s, a, r); v4[r * RXP] = s; }
        } else {
            const float* __restrict__ src = g ? yb : xb;
#pragma unroll
            for (int r = 0; r < RY; ++r) {
                int gr = row0 + r;
                bool ok = inw && ((unsigned)gr < IMG_H);
                a[r] = ok ? __ldg(src + gr * IMG_W + gc) : 0.0f;
            }
            float* __restrict__ vl = vp + g * SMEM_V + col;
#pragma unroll
            for (int r = 0; r < TY; ++r) { float s; TAP11(s, a, r); vl[r * RXP] = s; }
#pragma unroll
            for (int r = 0; r < RY; ++r) a[r] *= a[r];
            float* __restrict__ vs = vp + (2 + g) * SMEM_V + col;
#pragma unroll
            for (int r = 0; r < TY; ++r) { float s; TAP11(s, a, r); vs[r * RXP] = s; }
        }
    }
    __syncthreads();

    // ---- Phase C: horizontal blur + SSIM ----------------------------------
    // Task = (row, 4-col chunk): 16*32 = 512 tasks, exactly 2 per thread.
    // Lane stride 16B -> conflict-free LDS.128.
    const float C1 = 1e-4f;   // (0.01*1)^2
    const float C2 = 9e-4f;   // (0.03*1)^2
    float lsum = 0.0f;

#pragma unroll
    for (int it = 0; it < 2; ++it) {
        int T   = it * 256 + tid;
        int row = T >> 5;
        int c0  = (T & 31) << 2;

        float res[5][4];
#pragma unroll
        for (int q = 0; q < 5; ++q) {
            const float* __restrict__ base = vp + q * SMEM_V + row * RXP + c0;
            float w[16];
#pragma unroll
            for (int k = 0; k < 4; ++k) {
                float4 t4 = *reinterpret_cast<const float4*>(base + 4 * k);
                w[4 * k + 0] = t4.x;
                w[4 * k + 1] = t4.y;
                w[4 * k + 2] = t4.z;
                w[4 * k + 3] = t4.w;
            }
#pragma unroll
            for (int j = 0; j < 4; ++j) TAP11(res[q][j], w, j);
        }

#pragma unroll
        for (int j = 0; j < 4; ++j) {
            float mux  = res[0][j];
            float muy  = res[1][j];
            float mux2 = mux * mux;
            float muy2 = muy * muy;
            float muxy = mux * muy;
            float sx_  = res[2][j] - mux2;
            float sy_  = res[3][j] - muy2;
            float sxy_ = res[4][j] - muxy;
            float num = (2.0f * muxy + C1) * (2.0f * sxy_ + C2);
            float den = (mux2 + muy2 + C1) * (sx_ + sy_ + C2) + 1e-8f;
            lsum += __fdividef(num, den);
        }
    }

    // ---- Block reduce + global accumulate + last-block finalize -----------
#pragma unroll
    for (int o = 16; o; o >>= 1)
        lsum += __shfl_xor_sync(0xffffffffu, lsum, o);

    __shared__ float wsum[8];
    if ((tid & 31) == 0) wsum[tid >> 5] = lsum;
    __syncthreads();
    if (tid == 0) {
        float t = 0.0f;
#pragma unroll
        for (int i = 0; i < 8; ++i) t += wsum[i];
        atomicAdd(&g_accum, (double)t);
        __threadfence();
        unsigned int nb = gridDim.x * gridDim.y * gridDim.z;
        unsigned int tk = atomicAdd(&g_ticket, 1u);
        if (tk == nb - 1u) {
            double total = atomicAdd(&g_accum, 0.0);   // coherent L2 read
            out[0] = 1.0f - (float)(total * (double)inv_n);
            // Reset for next graph replay (deterministic across replays).
            g_accum  = 0.0;
            g_ticket = 0u;
        }
    }
}

extern "C" void kernel_launch(void* const* d_in, const int* in_sizes, int n_in,
                              void* d_out, int out_size) {
    const float* x = (const float*)d_in[0];
    const float* y = (const float*)d_in[1];
    float* out = (float*)d_out;

    const int planes = in_sizes[0] / (IMG_H * IMG_W);   // 48 = 16 batch * 3 ch
    const float inv_n = 1.0f / (float)in_sizes[0];

    dim3 grid(IMG_W / TX, IMG_H / TY, planes);   // 4 x 32 x 48 = 6144 blocks
    ssim_fused_kernel<<<grid, 256, SMEM_BYTES>>>(x, y, out, inv_n);
}